// round 14
// baseline (speedup 1.0000x reference)
#include <cuda_runtime.h>

#define NPTS    8192
#define TILE    256
#define NSPLIT  32             // JCHUNK == TILE == 256
#define NIBLK   (NPTS / TILE)  // 32 i-blocks
#define GAMMA_  100.0f         // 1 / sigma^2, sigma = 0.1
#define LOG2E   1.4426950408889634f

// Persistent accumulators (zero at module load; reset to zero each replay by
// the last-arriving CTA, so every replay starts from zero). 196 KB -> L2.
__device__ float g_acc[NPTS * 6];
__device__ int   g_cnt[NIBLK];   // arrival counter per i-block; self-resetting

// smem per j (recentered coords): A = (xt0, xt1, xt2, s2j), s2j = -g*l*|xt_j|^2
//                                  B = (pj0, pj1, pj2, 0)
__global__ __launch_bounds__(TILE)
void lddmm_kernel(const float* __restrict__ mom,
                  const float* __restrict__ x,
                  float* __restrict__ out)
{
    __shared__ float4 sA[TILE];
    __shared__ float4 sB[TILE];
    __shared__ int s_last;

    const int tid   = threadIdx.x;
    const int i     = blockIdx.x * TILE + tid;
    const int jbase = blockIdx.y * TILE;

    // ---- fill tile ----
    {
        const int j = jbase + tid;
        const float a0 = x[3*j] - 0.5f, a1 = x[3*j+1] - 0.5f, a2 = x[3*j+2] - 0.5f;
        const float s2 = -GAMMA_ * LOG2E * (a0*a0 + a1*a1 + a2*a2);
        sA[tid] = make_float4(a0, a1, a2, s2);
        sB[tid] = make_float4(mom[3*j], mom[3*j+1], mom[3*j+2], 0.f);
    }

    // ---- per-i loop invariants (recentered) ----
    const float xt0 = x[3*i] - 0.5f, xt1 = x[3*i+1] - 0.5f, xt2 = x[3*i+2] - 0.5f;
    const float pi0 = mom[3*i], pi1 = mom[3*i+1], pi2 = mom[3*i+2];
    const float g2l = 2.0f * GAMMA_ * LOG2E;
    const float gx0 = g2l * xt0, gx1 = g2l * xt1, gx2 = g2l * xt2;
    const float aiv = -GAMMA_ * LOG2E * (xt0*xt0 + xt1*xt1 + xt2*xt2);

    // accumulate with E = 2^(s2j + gx.xj) = K / Ci,  Ci = 2^aiv  (exact factoring)
    float dx0 = 0.f, dx1 = 0.f, dx2 = 0.f;   // sum E*pj
    float q0  = 0.f, q1  = 0.f, q2  = 0.f;   // sum E*pd*xt_j

    __syncthreads();

    #pragma unroll 8
    for (int k = 0; k < TILE; k++) {
        const float4 XJ = sA[k];             // LDS.128 broadcast
        const float4 PJ = sB[k];

        float arg = fmaf(gx0, XJ.x, XJ.w);   // 3 FFMA, no bias add
        arg = fmaf(gx1, XJ.y, arg);
        arg = fmaf(gx2, XJ.z, arg);

        float Ev;
        asm("ex2.approx.f32 %0, %1;" : "=f"(Ev) : "f"(arg));

        float pd = pi0 * PJ.x;
        pd = fmaf(pi1, PJ.y, pd);
        pd = fmaf(pi2, PJ.z, pd);
        const float w = Ev * pd;

        dx0 = fmaf(Ev, PJ.x, dx0);
        dx1 = fmaf(Ev, PJ.y, dx1);
        dx2 = fmaf(Ev, PJ.z, dx2);
        q0  = fmaf(w, XJ.x, q0);
        q1  = fmaf(w, XJ.y, q1);
        q2  = fmaf(w, XJ.z, q2);
    }

    // ---- epilogue: rescale by Ci, finalize this split's contribution ----
    const float Ci = exp2f(aiv);
    const float DX0 = Ci * dx0, DX1 = Ci * dx1, DX2 = Ci * dx2;
    const float Q0  = Ci * q0,  Q1  = Ci * q1,  Q2  = Ci * q2;
    const float ws  = pi0 * DX0 + pi1 * DX1 + pi2 * DX2;   // = sum K <pi,pj>
    const float cc  = 2.0f * GAMMA_;

    // commutative combine into persistent scratch (starts at zero each replay)
    float* acc = &g_acc[i * 6];
    atomicAdd(&acc[0], cc * fmaf(xt0, ws, -Q0));
    atomicAdd(&acc[1], cc * fmaf(xt1, ws, -Q1));
    atomicAdd(&acc[2], cc * fmaf(xt2, ws, -Q2));
    atomicAdd(&acc[3], DX0);
    atomicAdd(&acc[4], DX1);
    atomicAdd(&acc[5], DX2);

    // ---- last-arriving CTA per i-block: scratch -> out, reset scratch ----
    __threadfence();
    __syncthreads();
    if (tid == 0)
        s_last = (atomicAdd(&g_cnt[blockIdx.x], 1) == NSPLIT - 1) ? 1 : 0;
    __syncthreads();

    if (s_last) {
        __threadfence();                      // acquire: see all splits' adds
        #pragma unroll
        for (int c = 0; c < 3; c++) {
            out[3*i + c]          = __ldcg(&acc[c]);      // dmom (overwrites poison)
            out[3*NPTS + 3*i + c] = __ldcg(&acc[3 + c]);  // dx
            acc[c]     = 0.f;                 // ready for next replay
            acc[3 + c] = 0.f;
        }
        if (tid == 0) g_cnt[blockIdx.x] = 0;
    }
}

extern "C" void kernel_launch(void* const* d_in, const int* in_sizes, int n_in,
                              void* d_out, int out_size)
{
    const float* mom = (const float*)d_in[0];   // [1, 8192, 3]
    const float* x   = (const float*)d_in[1];   // [1, 8192, 3]
    float*       out = (float*)d_out;           // [2, 8192, 3] = dmom | dx

    dim3 grid(NIBLK, NSPLIT);                   // (32, 32) = 1024 CTAs, single launch
    lddmm_kernel<<<grid, TILE>>>(mom, x, out);
}

// round 15
// speedup vs baseline: 1.0799x; 1.0799x over previous
#include <cuda_runtime.h>

#define NPTS   8192
#define TILE   256
#define NSPLIT 32              // JCHUNK == TILE == 256
#define GAMMA_ 100.0f          // 1 / sigma^2, sigma = 0.1
#define LOG2E  1.4426950408889634f

// smem per j (recentered coords): A = (xt0, xt1, xt2, s2j), s2j = -g*l*|xt_j|^2
//                                  B = (pj0, pj1, pj2, 0)
__global__ __launch_bounds__(TILE)
void lddmm_kernel(const float* __restrict__ mom,
                  const float* __restrict__ x,
                  float* __restrict__ out)
{
    __shared__ float4 sA[TILE];
    __shared__ float4 sB[TILE];

    const int tid   = threadIdx.x;
    const int i     = blockIdx.x * TILE + tid;
    const int jbase = blockIdx.y * TILE;

    // ---- fill tile ----
    {
        const int j = jbase + tid;
        const float a0 = x[3*j] - 0.5f, a1 = x[3*j+1] - 0.5f, a2 = x[3*j+2] - 0.5f;
        const float s2 = -GAMMA_ * LOG2E * (a0*a0 + a1*a1 + a2*a2);
        sA[tid] = make_float4(a0, a1, a2, s2);
        sB[tid] = make_float4(mom[3*j], mom[3*j+1], mom[3*j+2], 0.f);
    }

    // ---- per-i loop invariants (recentered) ----
    const float xt0 = x[3*i] - 0.5f, xt1 = x[3*i+1] - 0.5f, xt2 = x[3*i+2] - 0.5f;
    const float pi0 = mom[3*i], pi1 = mom[3*i+1], pi2 = mom[3*i+2];
    const float g2l = 2.0f * GAMMA_ * LOG2E;
    const float gx0 = g2l * xt0, gx1 = g2l * xt1, gx2 = g2l * xt2;
    const float aiv = -GAMMA_ * LOG2E * (xt0*xt0 + xt1*xt1 + xt2*xt2);

    // accumulate with E = 2^(s2j + gx.xj) = K / Ci,  Ci = 2^aiv  (exact factoring)
    float dx0 = 0.f, dx1 = 0.f, dx2 = 0.f;   // sum E*pj
    float q0  = 0.f, q1  = 0.f, q2  = 0.f;   // sum E*pd*xt_j

    __syncthreads();

    #pragma unroll 8
    for (int k = 0; k < TILE; k++) {
        const float4 XJ = sA[k];             // LDS.128 broadcast
        const float4 PJ = sB[k];

        float arg = fmaf(gx0, XJ.x, XJ.w);   // 3 FFMA, no bias add
        arg = fmaf(gx1, XJ.y, arg);
        arg = fmaf(gx2, XJ.z, arg);

        float Ev;
        asm("ex2.approx.f32 %0, %1;" : "=f"(Ev) : "f"(arg));

        float pd = pi0 * PJ.x;
        pd = fmaf(pi1, PJ.y, pd);
        pd = fmaf(pi2, PJ.z, pd);
        const float w = Ev * pd;

        dx0 = fmaf(Ev, PJ.x, dx0);
        dx1 = fmaf(Ev, PJ.y, dx1);
        dx2 = fmaf(Ev, PJ.z, dx2);
        q0  = fmaf(w, XJ.x, q0);
        q1  = fmaf(w, XJ.y, q1);
        q2  = fmaf(w, XJ.z, q2);
    }

    // ---- epilogue: rescale by Ci, finalize, combine across splits ----
    const float Ci = exp2f(aiv);
    const float DX0 = Ci * dx0, DX1 = Ci * dx1, DX2 = Ci * dx2;
    const float Q0  = Ci * q0,  Q1  = Ci * q1,  Q2  = Ci * q2;

    const float ws = pi0 * DX0 + pi1 * DX1 + pi2 * DX2;   // = sum K <pi,pj>
    const float cc = 2.0f * GAMMA_;
    atomicAdd(&out[3*i + 0], cc * fmaf(xt0, ws, -Q0));    // dmom (shift cancels)
    atomicAdd(&out[3*i + 1], cc * fmaf(xt1, ws, -Q1));
    atomicAdd(&out[3*i + 2], cc * fmaf(xt2, ws, -Q2));
    atomicAdd(&out[3*NPTS + 3*i + 0], DX0);               // dx
    atomicAdd(&out[3*NPTS + 3*i + 1], DX1);
    atomicAdd(&out[3*NPTS + 3*i + 2], DX2);
}

extern "C" void kernel_launch(void* const* d_in, const int* in_sizes, int n_in,
                              void* d_out, int out_size)
{
    const float* mom = (const float*)d_in[0];   // [1, 8192, 3]
    const float* x   = (const float*)d_in[1];   // [1, 8192, 3]
    float*       out = (float*)d_out;           // [2, 8192, 3] = dmom | dx

    // Zero the (poisoned) output via an async memset node — cheaper than a
    // kernel launch; fp32 0.0f is all-zero bytes. Graph-capturable.
    cudaMemsetAsync(out, 0, (size_t)out_size * sizeof(float));

    dim3 grid(NPTS / TILE, NSPLIT);             // (32, 32) = 1024 CTAs
    lddmm_kernel<<<grid, TILE>>>(mom, x, out);
}

// round 17
// speedup vs baseline: 1.4944x; 1.3839x over previous
#include <cuda_runtime.h>
#include <cuda_fp16.h>
#include <cstdint>

#define NPTS    8192
#define ITILE   128
#define JTILE   128
#define SPLITS  16
#define TPC     4              // j-tiles per CTA: 4*128*16 = 8192
#define GAMMA_  100.0f
#define LOG2E   1.4426950408889634f
#define VSTRIDE 272            // V row stride (bytes): 68 u32 -> conflict-free B loads
#define ESTRIDE 26             // epi row stride (floats)

// V column layout (24 cols): 0-2 pj hi, 3-5 pj lo, 6+3d+c (pj_d*xt_c) hi, 15+3d+c lo
__device__ __forceinline__ void vput(char* sV, int chi, int clo, int jl, float v) {
    const __half h = __float2half_rn(v);
    *(__half*)(sV + chi * VSTRIDE + jl * 2) = h;
    *(__half*)(sV + clo * VSTRIDE + jl * 2) = __float2half_rn(v - __half2float(h));
}

__global__ __launch_bounds__(256, 3)
void lddmm_mma(const float* __restrict__ mom, const float* __restrict__ x,
               float* __restrict__ out)
{
    __shared__ __align__(16) char smem[13312];
    float4* sA = (float4*)smem;             // [128] (xt0, xt1, xt2, s2j)
    char*   sV = smem + 2048;               // f16 V^T [24][VSTRIDE]
    float*  sE = (float*)smem;              // epi [128][ESTRIDE], overlaps sA/sV

    const int tid  = threadIdx.x;
    const int wid  = tid >> 5;
    const int lane = tid & 31;
    const int qid  = lane >> 2;             // mma groupID (0..7)
    const int tq   = lane & 3;              // mma thread-in-group
    const int rloc = wid * 16 + qid;        // this thread's D rows: rloc, rloc+8

    // per-thread i constants for its two rows
    float gx0[2], gx1[2], gx2[2], av[2];
    #pragma unroll
    for (int h = 0; h < 2; h++) {
        const int ii = blockIdx.x * ITILE + rloc + h * 8;
        const float t0 = x[3*ii] - 0.5f, t1 = x[3*ii+1] - 0.5f, t2 = x[3*ii+2] - 0.5f;
        const float g2l = 2.0f * GAMMA_ * LOG2E;
        gx0[h] = g2l * t0; gx1[h] = g2l * t1; gx2[h] = g2l * t2;
        av[h]  = -GAMMA_ * LOG2E * (t0*t0 + t1*t1 + t2*t2);
    }

    float D[3][4];
    #pragma unroll
    for (int n = 0; n < 3; n++) { D[n][0] = D[n][1] = D[n][2] = D[n][3] = 0.f; }

    for (int t = 0; t < TPC; t++) {
        __syncthreads();
        if (tid < 128) {
            const int j = (blockIdx.y * TPC + t) * JTILE + tid;
            const float a0 = x[3*j] - 0.5f, a1 = x[3*j+1] - 0.5f, a2 = x[3*j+2] - 0.5f;
            sA[tid] = make_float4(a0, a1, a2,
                                  -GAMMA_ * LOG2E * (a0*a0 + a1*a1 + a2*a2));
            const float pv[3] = {mom[3*j], mom[3*j+1], mom[3*j+2]};
            const float xv[3] = {a0, a1, a2};
            #pragma unroll
            for (int d = 0; d < 3; d++) {
                vput(sV, d, d + 3, tid, pv[d]);
                #pragma unroll
                for (int c = 0; c < 3; c++)
                    vput(sV, 6 + 3*d + c, 15 + 3*d + c, tid, pv[d] * xv[c]);
            }
        }
        __syncthreads();

        #pragma unroll
        for (int kt = 0; kt < 8; kt++) {
            const int jb = kt * 16 + tq * 2;
            const float4 XA = sA[jb], XB = sA[jb + 1], XC = sA[jb + 8], XD = sA[jb + 9];
            uint32_t a[4];
            #pragma unroll
            for (int h = 0; h < 2; h++) {
                float g, kA, kB, kC, kD;
                g = fmaf(gx0[h], XA.x, fmaf(gx1[h], XA.y, fmaf(gx2[h], XA.z, XA.w))) + av[h];
                asm("ex2.approx.f32 %0, %1;" : "=f"(kA) : "f"(g));
                g = fmaf(gx0[h], XB.x, fmaf(gx1[h], XB.y, fmaf(gx2[h], XB.z, XB.w))) + av[h];
                asm("ex2.approx.f32 %0, %1;" : "=f"(kB) : "f"(g));
                g = fmaf(gx0[h], XC.x, fmaf(gx1[h], XC.y, fmaf(gx2[h], XC.z, XC.w))) + av[h];
                asm("ex2.approx.f32 %0, %1;" : "=f"(kC) : "f"(g));
                g = fmaf(gx0[h], XD.x, fmaf(gx1[h], XD.y, fmaf(gx2[h], XD.z, XD.w))) + av[h];
                asm("ex2.approx.f32 %0, %1;" : "=f"(kD) : "f"(g));
                asm("cvt.rn.f16x2.f32 %0, %1, %2;" : "=r"(a[h])     : "f"(kB), "f"(kA));
                asm("cvt.rn.f16x2.f32 %0, %1, %2;" : "=r"(a[2 + h]) : "f"(kD), "f"(kC));
            }
            const char* vb = sV + jb * 2;
            #pragma unroll
            for (int nt = 0; nt < 3; nt++) {
                const int c = 8 * nt + qid;                 // B col = groupID
                const uint32_t b0 = *(const uint32_t*)(vb + c * VSTRIDE);
                const uint32_t b1 = *(const uint32_t*)(vb + c * VSTRIDE + 16);
                asm volatile(
                    "mma.sync.aligned.m16n8k16.row.col.f32.f16.f16.f32 "
                    "{%0,%1,%2,%3}, {%4,%5,%6,%7}, {%8,%9}, {%0,%1,%2,%3};"
                    : "+f"(D[nt][0]), "+f"(D[nt][1]), "+f"(D[nt][2]), "+f"(D[nt][3])
                    : "r"(a[0]), "r"(a[1]), "r"(a[2]), "r"(a[3]), "r"(b0), "r"(b1));
            }
        }
    }

    // ---- epilogue: dump D frags to smem, then per-row finalize ----
    __syncthreads();
    #pragma unroll
    for (int nt = 0; nt < 3; nt++) {
        const int c0 = 8 * nt + 2 * tq;
        sE[rloc * ESTRIDE + c0]           = D[nt][0];
        sE[rloc * ESTRIDE + c0 + 1]       = D[nt][1];
        sE[(rloc + 8) * ESTRIDE + c0]     = D[nt][2];
        sE[(rloc + 8) * ESTRIDE + c0 + 1] = D[nt][3];
    }
    __syncthreads();

    if (tid < 128) {
        const int ii = blockIdx.x * ITILE + tid;
        const float* row = &sE[tid * ESTRIDE];
        float dxv[3], Mv[3][3];
        #pragma unroll
        for (int d = 0; d < 3; d++) dxv[d] = row[d] + row[3 + d];
        #pragma unroll
        for (int d = 0; d < 3; d++)
            #pragma unroll
            for (int c = 0; c < 3; c++)
                Mv[d][c] = row[6 + 3*d + c] + row[15 + 3*d + c];

        const float pi[3] = {mom[3*ii], mom[3*ii+1], mom[3*ii+2]};
        const float ti[3] = {x[3*ii] - 0.5f, x[3*ii+1] - 0.5f, x[3*ii+2] - 0.5f};
        const float ws = pi[0]*dxv[0] + pi[1]*dxv[1] + pi[2]*dxv[2];
        const float cc = 2.0f * GAMMA_;
        #pragma unroll
        for (int c = 0; c < 3; c++) {
            const float s = pi[0]*Mv[0][c] + pi[1]*Mv[1][c] + pi[2]*Mv[2][c];
            atomicAdd(&out[3*ii + c], cc * (ti[c] * ws - s));   // dmom
            atomicAdd(&out[3*NPTS + 3*ii + c], dxv[c]);         // dx
        }
    }
}

extern "C" void kernel_launch(void* const* d_in, const int* in_sizes, int n_in,
                              void* d_out, int out_size)
{
    const float* mom = (const float*)d_in[0];   // [1, 8192, 3]
    const float* x   = (const float*)d_in[1];   // [1, 8192, 3]
    float*       out = (float*)d_out;           // [2, 8192, 3] = dmom | dx

    cudaMemsetAsync(out, 0, (size_t)out_size * sizeof(float));

    dim3 grid(NPTS / ITILE, SPLITS);            // (64, 16) = 1024 CTAs
    lddmm_mma<<<grid, 256>>>(mom, x, out);
}